// round 7
// baseline (speedup 1.0000x reference)
#include <cuda_runtime.h>
#include <cstdint>

#define BN_EPS 1e-5f

static constexpr size_t SZ64 = (size_t)16 * 256 * 64 * 64;
static constexpr size_t SZ32 = (size_t)16 * 256 * 32 * 32;

__device__ float g_A64[SZ64];
__device__ float g_B32a[SZ32];
__device__ float g_B32b[SZ32];
__device__ float g_B32c[SZ32];
__device__ float g_mean[256];
__device__ float g_r[256];
__device__ float g_cnorm[512];
__device__ int   g_q[16384];

// ---- BN batch stats: mean + r = 1/sqrt(var+eps), jnp.var two-pass semantics ----
__global__ void bn_stats_kernel(const float* __restrict__ x,
                                float* __restrict__ mean_out,
                                float* __restrict__ r_out,
                                int N, int C, int HW)
{
    int c = blockIdx.x;
    int tx = threadIdx.x;
    __shared__ float red[256];
    __shared__ float s_m;
    float inv = 1.f / (float)(N * HW);          // exact (power of two)

    float s = 0.f;
    for (int n = 0; n < N; ++n) {
        const float* p = x + ((size_t)n * C + c) * HW;
        for (int i = tx; i < HW; i += 256) s += p[i];
    }
    red[tx] = s;
    __syncthreads();
    for (int o = 128; o > 0; o >>= 1) {
        if (tx < o) red[tx] += red[tx + o];
        __syncthreads();
    }
    if (tx == 0) s_m = red[0] * inv;
    __syncthreads();
    float m = s_m;

    float s2 = 0.f;
    for (int n = 0; n < N; ++n) {
        const float* p = x + ((size_t)n * C + c) * HW;
        for (int i = tx; i < HW; i += 256) {
            float d = __fsub_rn(p[i], m);
            s2 += __fmul_rn(d, d);
        }
    }
    red[tx] = s2;
    __syncthreads();
    for (int o = 128; o > 0; o >>= 1) {
        if (tx < o) red[tx] += red[tx + o];
        __syncthreads();
    }
    if (tx == 0) {
        float var = red[0] * inv;
        mean_out[c] = m;
        r_out[c] = __fdiv_rn(1.0f, __fsqrt_rn(__fadd_rn(var, BN_EPS)));
    }
}

// reference BN+ReLU elementwise form: relu((((x-m)*r)*g)+b)
__device__ __forceinline__ float bnrelu_apply(float v, float m, float r, float g, float b)
{
    float t = __fsub_rn(v, m);
    t = __fmul_rn(t, r);
    t = __fmul_rn(t, g);
    t = __fadd_rn(t, b);
    return fmaxf(t, 0.f);
}

// ---------------- direct conv ----------------
template<int KH, int KW, int S, int P, int CI, bool BNRELU, bool ADDRES>
__global__ void __launch_bounds__(256)
conv_kernel(const float* __restrict__ in, const float* __restrict__ wgt,
            const float* __restrict__ bias,
            const float* __restrict__ bmean, const float* __restrict__ br,
            const float* __restrict__ bg, const float* __restrict__ bb,
            const float* __restrict__ res, float* __restrict__ out,
            int N, int Cin, int Hin, int Win, int Cout, int Hout, int Wout)
{
    constexpr int TH = 8, TW = 16;
    constexpr int PH = (TH - 1) * S + KH;
    constexpr int PW = (TW - 1) * S + KW;
    constexpr int KC = CI * KH * KW;
    constexpr int WS = KC | 1;
    __shared__ float s_in[CI * PH * PW];
    __shared__ float s_w[64 * WS];

    int tilesW = Wout / TW, tilesH = Hout / TH;
    int tpi = tilesW * tilesH;
    int n  = blockIdx.x / tpi;
    int t  = blockIdx.x % tpi;
    int oh0 = (t / tilesW) * TH, ow0 = (t % tilesW) * TW;
    int co0 = blockIdx.y * 64;
    int tx  = threadIdx.x;
    int c   = tx & 15;
    int r   = tx >> 4;
    int row  = r >> 1;
    int owl0 = (r & 1) * 8;

    float acc[4][8];
#pragma unroll
    for (int j = 0; j < 4; ++j)
#pragma unroll
        for (int p = 0; p < 8; ++p) acc[j][p] = 0.f;

    int ihb = oh0 * S - P, iwb = ow0 * S - P;

#pragma unroll 1
    for (int ci0 = 0; ci0 < Cin; ci0 += CI) {
        __syncthreads();
#pragma unroll 1
        for (int idx = tx; idx < CI * PH * PW; idx += 256) {
            int ci  = idx / (PH * PW);
            int rem = idx - ci * (PH * PW);
            int lh  = rem / PW, lw = rem - lh * PW;
            int ih  = ihb + lh, iw = iwb + lw;
            int cg  = ci0 + ci;
            float v = 0.f;
            if (cg < Cin && (unsigned)ih < (unsigned)Hin && (unsigned)iw < (unsigned)Win) {
                v = in[(((size_t)n * Cin + cg) * Hin + ih) * Win + iw];
                if (BNRELU) v = bnrelu_apply(v, bmean[cg], br[cg], bg[cg], bb[cg]);
            }
            s_in[idx] = v;
        }
#pragma unroll 1
        for (int idx = tx; idx < 64 * KC; idx += 256) {
            int co  = idx / KC;
            int rem = idx - co * KC;
            int ci  = rem / (KH * KW);
            int k   = rem - ci * (KH * KW);
            int cg  = ci0 + ci;
            float v = (cg < Cin) ? wgt[(((size_t)(co0 + co) * Cin + cg) * (KH * KW)) + k] : 0.f;
            s_w[co * WS + rem] = v;
        }
        __syncthreads();
#pragma unroll 2
        for (int ci = 0; ci < CI; ++ci) {
#pragma unroll
            for (int kh = 0; kh < KH; ++kh) {
#pragma unroll
                for (int kw = 0; kw < KW; ++kw) {
                    const int k = (ci * KH + kh) * KW + kw;
                    float wv[4];
#pragma unroll
                    for (int j = 0; j < 4; ++j) wv[j] = s_w[(c + 16 * j) * WS + k];
                    const float* ip = &s_in[ci * PH * PW + (row * S + kh) * PW + owl0 * S + kw];
                    float iv[8];
#pragma unroll
                    for (int p = 0; p < 8; ++p) iv[p] = ip[p * S];
#pragma unroll
                    for (int j = 0; j < 4; ++j)
#pragma unroll
                        for (int p = 0; p < 8; ++p) acc[j][p] = fmaf(wv[j], iv[p], acc[j][p]);
                }
            }
        }
    }
    int oh = oh0 + row;
#pragma unroll
    for (int j = 0; j < 4; ++j) {
        int co = co0 + c + 16 * j;
        float bv = bias[co];
        size_t base = (((size_t)n * Cout + co) * Hout + oh) * Wout + ow0 + owl0;
#pragma unroll
        for (int p = 0; p < 8; ++p) {
            float v = __fadd_rn(acc[j][p], bv);
            if (ADDRES) v = __fadd_rn(v, res[base + p]);
            out[base + p] = v;
        }
    }
}

// ---------------- transposed conv k=4 s=2 p=1 ----------------
template<int CI, bool BNRELU>
__global__ void __launch_bounds__(256)
convT_kernel(const float* __restrict__ in, const float* __restrict__ wgt,
             const float* __restrict__ bias,
             const float* __restrict__ bmean, const float* __restrict__ br,
             const float* __restrict__ bg, const float* __restrict__ bb,
             float* __restrict__ out,
             int N, int Cin, int Hin, int Win, int Cout, int Hout, int Wout)
{
    constexpr int TH = 8, TW = 16;
    constexpr int PH = 6, PW = 10;
    constexpr int WS = (CI * 16) | 1;
    __shared__ float s_in[CI * PH * PW];
    __shared__ float s_w[64 * WS];

    int tilesW = Wout / TW, tilesH = Hout / TH;
    int tpi = tilesW * tilesH;
    int n  = blockIdx.x / tpi;
    int t  = blockIdx.x % tpi;
    int oh0 = (t / tilesW) * TH, ow0 = (t % tilesW) * TW;
    int co0 = blockIdx.y * 64;
    int tx  = threadIdx.x;
    int c   = tx & 15;
    int r   = tx >> 4;
    int row = r >> 1;
    int par = r & 1;

    int ih0 = (oh0 >> 1) - 1, iw0 = (ow0 >> 1) - 1;
    int khp = (row + 1) & 1;
    int kwp = 1 - par;

    float acc[4][8];
#pragma unroll
    for (int j = 0; j < 4; ++j)
#pragma unroll
        for (int p = 0; p < 8; ++p) acc[j][p] = 0.f;

#pragma unroll 1
    for (int ci0 = 0; ci0 < Cin; ci0 += CI) {
        __syncthreads();
#pragma unroll 1
        for (int idx = tx; idx < CI * PH * PW; idx += 256) {
            int ci  = idx / (PH * PW);
            int rem = idx - ci * (PH * PW);
            int lh  = rem / PW, lw = rem - lh * PW;
            int ih  = ih0 + lh, iw = iw0 + lw;
            int cg  = ci0 + ci;
            float v = 0.f;
            if ((unsigned)ih < (unsigned)Hin && (unsigned)iw < (unsigned)Win) {
                v = in[(((size_t)n * Cin + cg) * Hin + ih) * Win + iw];
                if (BNRELU) v = bnrelu_apply(v, bmean[cg], br[cg], bg[cg], bb[cg]);
            }
            s_in[idx] = v;
        }
#pragma unroll 1
        for (int idx = tx; idx < 64 * CI * 16; idx += 256) {
            int co  = idx / (CI * 16);
            int rem = idx - co * (CI * 16);
            int ci  = rem >> 4;
            int k   = rem & 15;
            s_w[co * WS + rem] = wgt[(((size_t)(ci0 + ci) * Cout + co0 + co) << 4) + k];
        }
        __syncthreads();
#pragma unroll 2
        for (int ci = 0; ci < CI; ++ci) {
#pragma unroll
            for (int a = 0; a < 2; ++a) {
                int kh  = khp + 2 * a;
                int ihl = ((row + 1) >> 1) + 1 - a;
#pragma unroll
                for (int b = 0; b < 2; ++b) {
                    int kw = kwp + 2 * b;
                    float wv[4];
#pragma unroll
                    for (int j = 0; j < 4; ++j) wv[j] = s_w[(c + 16 * j) * WS + ci * 16 + kh * 4 + kw];
                    const float* ip = &s_in[ci * PH * PW + ihl * PW + par + 1 - b];
                    float iv[8];
#pragma unroll
                    for (int p = 0; p < 8; ++p) iv[p] = ip[p];
#pragma unroll
                    for (int j = 0; j < 4; ++j)
#pragma unroll
                        for (int p = 0; p < 8; ++p) acc[j][p] = fmaf(wv[j], iv[p], acc[j][p]);
                }
            }
        }
    }
    int oh = oh0 + row;
#pragma unroll
    for (int j = 0; j < 4; ++j) {
        int co = co0 + c + 16 * j;
        float bv = bias[co];
        size_t base = (((size_t)n * Cout + co) * Hout + oh) * Wout + ow0 + par;
#pragma unroll
        for (int p = 0; p < 8; ++p)
            out[base + 2 * p] = __fadd_rn(acc[j][p], bv);
    }
}

// ---------------- final transposed conv to 3 channels ----------------
__global__ void __launch_bounds__(256)
convT_out_kernel(const float* __restrict__ in, const float* __restrict__ wgt,
                 const float* __restrict__ bias,
                 const float* __restrict__ bmean, const float* __restrict__ br,
                 const float* __restrict__ bg, const float* __restrict__ bb,
                 float* __restrict__ out,
                 int N, int Cin, int Hin, int Win, int Hout, int Wout)
{
    constexpr int CI = 16;
    __shared__ float s_in[CI * 100];
    __shared__ float s_w[CI * 48];
    int tilesW = Wout / 16;
    int tpi = tilesW * (Hout / 16);
    int n  = blockIdx.x / tpi;
    int t  = blockIdx.x % tpi;
    int oh0 = (t / tilesW) * 16, ow0 = (t % tilesW) * 16;
    int tx  = threadIdx.x;
    int row = tx >> 4, col = tx & 15;
    int oh = oh0 + row, ow = ow0 + col;
    int khp = (oh + 1) & 1, kwp = (ow + 1) & 1;
    int ih0 = (oh0 >> 1) - 1, iw0 = (ow0 >> 1) - 1;
    float acc[3] = {0.f, 0.f, 0.f};

#pragma unroll 1
    for (int ci0 = 0; ci0 < Cin; ci0 += CI) {
        __syncthreads();
#pragma unroll 1
        for (int idx = tx; idx < CI * 100; idx += 256) {
            int ci  = idx / 100;
            int rem = idx - ci * 100;
            int lh  = rem / 10, lw = rem - lh * 10;
            int ih  = ih0 + lh, iw = iw0 + lw;
            float v = 0.f;
            if ((unsigned)ih < (unsigned)Hin && (unsigned)iw < (unsigned)Win) {
                int cg = ci0 + ci;
                v = in[(((size_t)n * Cin + cg) * Hin + ih) * Win + iw];
                v = bnrelu_apply(v, bmean[cg], br[cg], bg[cg], bb[cg]);
            }
            s_in[idx] = v;
        }
#pragma unroll 1
        for (int idx = tx; idx < CI * 48; idx += 256) {
            int ci  = idx / 48;
            int rem = idx - ci * 48;
            s_w[idx] = wgt[(size_t)(ci0 + ci) * 48 + rem];
        }
        __syncthreads();
#pragma unroll 2
        for (int ci = 0; ci < CI; ++ci) {
#pragma unroll
            for (int a = 0; a < 2; ++a) {
                int ihl = ((oh + 1) >> 1) - a - ih0;
                int kh  = khp + 2 * a;
#pragma unroll
                for (int b = 0; b < 2; ++b) {
                    int iwl = ((ow + 1) >> 1) - b - iw0;
                    int kw  = kwp + 2 * b;
                    float iv = s_in[ci * 100 + ihl * 10 + iwl];
#pragma unroll
                    for (int co = 0; co < 3; ++co)
                        acc[co] = fmaf(s_w[ci * 48 + co * 16 + kh * 4 + kw], iv, acc[co]);
                }
            }
        }
    }
#pragma unroll
    for (int co = 0; co < 3; ++co)
        out[(((size_t)n * 3 + co) * Hout + oh) * Wout + ow] = __fadd_rn(acc[co], bias[co]);
}

// ---------------- VQ: replicate reference fp32 numerics ----------------
// d2 = fl( fl(Z_m - B_mk) + cn_k ); B = (2z)@cb.T sequential-d fma chain;
// Z = sum of rounded squares, sequential d; argmin first-index.
__global__ void cnorm_kernel(const float* __restrict__ cb, float* __restrict__ cn)
{
    int k = blockIdx.x * blockDim.x + threadIdx.x;
    if (k < 512) {
        const float* p = cb + (size_t)k * 256;
        float acc = 0.f;
#pragma unroll 4
        for (int d = 0; d < 256; ++d)
            acc = __fadd_rn(acc, __fmul_rn(p[d], p[d]));
        cn[k] = acc;
    }
}

__global__ void __launch_bounds__(256)
vq_argmin_kernel(const float* __restrict__ z, const float* __restrict__ cb,
                 const float* __restrict__ cn, int* __restrict__ q)
{
    __shared__ float s_z[32 * 257];    // 2*z transposed
    __shared__ float s_Z[32];
    __shared__ float s_bd[256];
    __shared__ int   s_bi[256];
    int nh = blockIdx.x;
    int n = nh >> 5, h = nh & 31;
    int tx = threadIdx.x;
    size_t zb = (size_t)n * 262144 + (size_t)h * 32;
#pragma unroll 1
    for (int idx = tx; idx < 256 * 32; idx += 256) {
        int d = idx >> 5, w = idx & 31;
        s_z[w * 257 + d] = 2.0f * z[zb + (size_t)d * 1024 + w];   // exact x2
    }
    __syncthreads();
    // Z_m: sequential chain of rounded squares (0.5x recovers z exactly)
    if (tx < 32) {
        const float* zr = s_z + tx * 257;
        float acc = 0.f;
#pragma unroll 4
        for (int d = 0; d < 256; ++d) {
            float zv = 0.5f * zr[d];
            acc = __fadd_rn(acc, __fmul_rn(zv, zv));
        }
        s_Z[tx] = acc;
    }
    __syncthreads();

    int m = tx & 31, g = tx >> 5;
    const float* zr = s_z + m * 257;
    float Zm = s_Z[m];
    float best = 3.4028235e38f;
    int bi = 0;
#pragma unroll 1
    for (int t = 0; t < 64; t += 2) {
        int k0 = g + 8 * t;
        int k1 = k0 + 8;
        const float* c0 = cb + (size_t)k0 * 256;
        const float* c1 = cb + (size_t)k1 * 256;
        float A = 0.f, B = 0.f;   // two independent sequential chains
#pragma unroll 4
        for (int d = 0; d < 256; ++d) {
            float zv = zr[d];
            A = fmaf(zv, c0[d], A);
            B = fmaf(zv, c1[d], B);
        }
        float t0 = __fadd_rn(__fsub_rn(Zm, A), cn[k0]);
        float t1 = __fadd_rn(__fsub_rn(Zm, B), cn[k1]);
        if (t0 < best) { best = t0; bi = k0; }
        if (t1 < best) { best = t1; bi = k1; }
    }
    s_bd[g * 32 + m] = best;
    s_bi[g * 32 + m] = bi;
    __syncthreads();
    if (tx < 32) {
        float bb = s_bd[tx];
        int   ii = s_bi[tx];
#pragma unroll
        for (int gg = 1; gg < 8; ++gg) {
            float dd = s_bd[gg * 32 + tx];
            int   jj = s_bi[gg * 32 + tx];
            if (dd < bb || (dd == bb && jj < ii)) { bb = dd; ii = jj; }
        }
        q[nh * 32 + tx] = ii;
    }
}

__global__ void vq_gather_kernel(const int* __restrict__ q, const float* __restrict__ cb,
                                 float* __restrict__ zq)
{
    __shared__ int s_q[32];
    int nh = blockIdx.x;
    int n = nh >> 5, h = nh & 31;
    int tx = threadIdx.x;
    if (tx < 32) s_q[tx] = q[nh * 32 + tx];
    __syncthreads();
    size_t zb = (size_t)n * 262144 + (size_t)h * 32;
#pragma unroll 1
    for (int idx = tx; idx < 256 * 32; idx += 256) {
        int d = idx >> 5, w = idx & 31;
        zq[zb + (size_t)d * 1024 + w] = cb[(size_t)s_q[w] * 256 + d];
    }
}

// ---------------- host ----------------
static void run_resblock(const float* X, float* T, float* Y,
                         const float* bn1g, const float* bn1b,
                         const float* c3w, const float* c3b,
                         const float* bn2g, const float* bn2b,
                         const float* c1w, const float* c1b,
                         float* mn, float* rr)
{
    dim3 grid(16 * 8, 4);
    bn_stats_kernel<<<256, 256>>>(X, mn, rr, 16, 256, 1024);
    conv_kernel<3, 3, 1, 1, 8, true, false><<<grid, 256>>>(
        X, c3w, c3b, mn, rr, bn1g, bn1b, nullptr, T, 16, 256, 32, 32, 256, 32, 32);
    bn_stats_kernel<<<256, 256>>>(T, mn, rr, 16, 256, 1024);
    conv_kernel<1, 1, 1, 0, 32, true, true><<<grid, 256>>>(
        T, c1w, c1b, mn, rr, bn2g, bn2b, X, Y, 16, 256, 32, 32, 256, 32, 32);
}

extern "C" void kernel_launch(void* const* d_in, const int* in_sizes, int n_in,
                              void* d_out, int out_size)
{
    (void)in_sizes; (void)n_in; (void)out_size;
    const float* x        = (const float*)d_in[0];
    const float* ec1_w    = (const float*)d_in[1];
    const float* ec1_b    = (const float*)d_in[2];
    const float* ebn1_g   = (const float*)d_in[3];
    const float* ebn1_b   = (const float*)d_in[4];
    const float* ec2_w    = (const float*)d_in[5];
    const float* ec2_b    = (const float*)d_in[6];
    const float* rb_bn1_g = (const float*)d_in[7];
    const float* rb_bn1_b = (const float*)d_in[8];
    const float* rb_c3_w  = (const float*)d_in[9];
    const float* rb_c3_b  = (const float*)d_in[10];
    const float* rb_bn2_g = (const float*)d_in[11];
    const float* rb_bn2_b = (const float*)d_in[12];
    const float* rb_c1_w  = (const float*)d_in[13];
    const float* rb_c1_b  = (const float*)d_in[14];
    const float* dbn1_g   = (const float*)d_in[15];
    const float* dbn1_b   = (const float*)d_in[16];
    const float* dct1_w   = (const float*)d_in[17];
    const float* dct1_b   = (const float*)d_in[18];
    const float* dbn2_g   = (const float*)d_in[19];
    const float* dbn2_b   = (const float*)d_in[20];
    const float* dct2_w   = (const float*)d_in[21];
    const float* dct2_b   = (const float*)d_in[22];
    const float* codebook = (const float*)d_in[23];

    float *A64, *Ba, *Bb, *Bc, *mn, *rr, *cn;
    int* q;
    cudaGetSymbolAddress((void**)&A64, g_A64);
    cudaGetSymbolAddress((void**)&Ba,  g_B32a);
    cudaGetSymbolAddress((void**)&Bb,  g_B32b);
    cudaGetSymbolAddress((void**)&Bc,  g_B32c);
    cudaGetSymbolAddress((void**)&mn,  g_mean);
    cudaGetSymbolAddress((void**)&rr,  g_r);
    cudaGetSymbolAddress((void**)&cn,  g_cnorm);
    cudaGetSymbolAddress((void**)&q,   g_q);

    float* out   = (float*)d_out;
    float* x_rec = out;
    float* z_e   = out + 786432;
    float* z_q   = z_e + 4194304;

    // encoder
    conv_kernel<4, 4, 2, 1, 4, false, false><<<dim3(16 * 32, 4), 256>>>(
        x, ec1_w, ec1_b, nullptr, nullptr, nullptr, nullptr, nullptr, A64,
        16, 3, 128, 128, 256, 64, 64);
    bn_stats_kernel<<<256, 256>>>(A64, mn, rr, 16, 256, 4096);
    conv_kernel<4, 4, 2, 1, 4, true, false><<<dim3(16 * 8, 4), 256>>>(
        A64, ec2_w, ec2_b, mn, rr, ebn1_g, ebn1_b, nullptr, Ba,
        16, 256, 64, 64, 256, 32, 32);

    const size_t W3 = (size_t)256 * 256 * 9;
    const size_t W1 = (size_t)256 * 256;
    run_resblock(Ba, Bb, Bc, rb_bn1_g + 0, rb_bn1_b + 0, rb_c3_w + 0 * W3, rb_c3_b + 0,
                 rb_bn2_g + 0, rb_bn2_b + 0, rb_c1_w + 0 * W1, rb_c1_b + 0, mn, rr);
    run_resblock(Bc, Bb, z_e, rb_bn1_g + 256, rb_bn1_b + 256, rb_c3_w + 1 * W3, rb_c3_b + 256,
                 rb_bn2_g + 256, rb_bn2_b + 256, rb_c1_w + 1 * W1, rb_c1_b + 256, mn, rr);

    // VQ
    cnorm_kernel<<<2, 256>>>(codebook, cn);
    vq_argmin_kernel<<<512, 256>>>(z_e, codebook, cn, q);
    vq_gather_kernel<<<512, 256>>>(q, codebook, z_q);

    // decoder
    run_resblock(z_e, Ba, Bb, rb_bn1_g + 512, rb_bn1_b + 512, rb_c3_w + 2 * W3, rb_c3_b + 512,
                 rb_bn2_g + 512, rb_bn2_b + 512, rb_c1_w + 2 * W1, rb_c1_b + 512, mn, rr);
    run_resblock(Bb, Bc, Ba, rb_bn1_g + 768, rb_bn1_b + 768, rb_c3_w + 3 * W3, rb_c3_b + 768,
                 rb_bn2_g + 768, rb_bn2_b + 768, rb_c1_w + 3 * W1, rb_c1_b + 768, mn, rr);

    bn_stats_kernel<<<256, 256>>>(Ba, mn, rr, 16, 256, 1024);
    convT_kernel<8, true><<<dim3(16 * 32, 4), 256>>>(
        Ba, dct1_w, dct1_b, mn, rr, dbn1_g, dbn1_b, A64,
        16, 256, 32, 32, 256, 64, 64);
    bn_stats_kernel<<<256, 256>>>(A64, mn, rr, 16, 256, 4096);
    convT_out_kernel<<<16 * 64, 256>>>(
        A64, dct2_w, dct2_b, mn, rr, dbn2_g, dbn2_b, x_rec,
        16, 256, 64, 64, 128, 128);
}